// round 6
// baseline (speedup 1.0000x reference)
#include <cuda_runtime.h>
#include <math.h>

// Single fused kernel: grid-stride streaming reduction + last-block-done
// final fold. Mainloop restored to the R2-measured configuration
// (plain float4 loads, no unroll pragma, no __ldcs).

constexpr int NBLK = 2048;
constexpr int NTHR = 256;

struct Part {
    float s0, m0, s1, s2;
};

__device__ Part g_part[NBLK];
__device__ unsigned int g_count;  // zero-initialized; reset by finisher

__device__ __forceinline__ float fix_len(float l) {
    return isfinite(l) ? l : 0.0f;
}

__device__ __forceinline__ void warp_red(float& s0, float& s1, float& s2, float& m0) {
    #pragma unroll
    for (int o = 16; o > 0; o >>= 1) {
        s0 += __shfl_xor_sync(0xffffffffu, s0, o);
        s1 += __shfl_xor_sync(0xffffffffu, s1, o);
        s2 += __shfl_xor_sync(0xffffffffu, s2, o);
        m0 = fmaxf(m0, __shfl_xor_sync(0xffffffffu, m0, o));
    }
}

__global__ __launch_bounds__(NTHR) void toploss_fused(
    const float4* __restrict__ a,
    const float4* __restrict__ b,
    const float4* __restrict__ c,
    float* __restrict__ out,
    int nvec)
{
    float s0 = 0.0f, s1 = 0.0f, s2 = 0.0f;
    float m0 = -INFINITY;

    const int stride = gridDim.x * blockDim.x;
    for (int i = blockIdx.x * blockDim.x + threadIdx.x; i < nvec; i += stride) {
        float4 va = a[i];
        float4 vb = b[i];
        float4 vc = c[i];

        float la0 = fix_len(va.x - va.y);
        float la1 = fix_len(va.z - va.w);
        s0 = fmaf(la0, la0, s0);
        s0 = fmaf(la1, la1, s0);
        m0 = fmaxf(m0, fmaxf(la0, la1));

        float lb0 = fix_len(vb.x - vb.y);
        float lb1 = fix_len(vb.z - vb.w);
        s1 = fmaf(lb0, lb0, s1);
        s1 = fmaf(lb1, lb1, s1);

        float lc0 = fix_len(vc.x - vc.y);
        float lc1 = fix_len(vc.z - vc.w);
        s2 = fmaf(lc0, lc0, s2);
        s2 = fmaf(lc1, lc1, s2);
    }

    // ---- intra-block reduce ----
    warp_red(s0, s1, s2, m0);

    __shared__ float sh_s0[NTHR / 32], sh_s1[NTHR / 32], sh_s2[NTHR / 32], sh_m0[NTHR / 32];
    __shared__ bool sh_last;

    const int lane = threadIdx.x & 31;
    const int wid  = threadIdx.x >> 5;
    if (lane == 0) {
        sh_s0[wid] = s0;
        sh_s1[wid] = s1;
        sh_s2[wid] = s2;
        sh_m0[wid] = m0;
    }
    __syncthreads();

    if (threadIdx.x == 0) {
        constexpr int NW = NTHR / 32;
        float rs0 = sh_s0[0], rs1 = sh_s1[0], rs2 = sh_s2[0], rm0 = sh_m0[0];
        #pragma unroll
        for (int w = 1; w < NW; w++) {
            rs0 += sh_s0[w];
            rs1 += sh_s1[w];
            rs2 += sh_s2[w];
            rm0 = fmaxf(rm0, sh_m0[w]);
        }
        Part p;
        p.s0 = rs0; p.m0 = rm0; p.s1 = rs1; p.s2 = rs2;
        g_part[blockIdx.x] = p;
        __threadfence();
        unsigned int prev = atomicAdd(&g_count, 1u);
        sh_last = (prev == (unsigned int)(NBLK - 1));
    }
    __syncthreads();

    if (!sh_last) return;

    // ---- final fold by the last-finishing block (fixed order) ----
    constexpr int PER = NBLK / NTHR;  // 8 partials per thread
    float fs0 = 0.0f, fs1 = 0.0f, fs2 = 0.0f;
    float fm0 = -INFINITY;
    #pragma unroll
    for (int j = 0; j < PER; j++) {
        Part p = g_part[threadIdx.x * PER + j];
        fs0 += p.s0;
        fs1 += p.s1;
        fs2 += p.s2;
        fm0 = fmaxf(fm0, p.m0);
    }

    warp_red(fs0, fs1, fs2, fm0);

    __shared__ float fh_s0[NTHR / 32], fh_s1[NTHR / 32], fh_s2[NTHR / 32], fh_m0[NTHR / 32];
    if (lane == 0) {
        fh_s0[wid] = fs0;
        fh_s1[wid] = fs1;
        fh_s2[wid] = fs2;
        fh_m0[wid] = fm0;
    }
    __syncthreads();

    if (threadIdx.x == 0) {
        constexpr int NW = NTHR / 32;
        float rs0 = fh_s0[0], rs1 = fh_s1[0], rs2 = fh_s2[0], rm0 = fh_m0[0];
        #pragma unroll
        for (int w = 1; w < NW; w++) {
            rs0 += fh_s0[w];
            rs1 += fh_s1[w];
            rs2 += fh_s2[w];
            rm0 = fmaxf(rm0, fh_m0[w]);
        }

        float top1sq = rm0 * rm0;
        float t01 = 1.0f - top1sq;   // sum(1 - top1^2), one element
        float t0  = rs0 - top1sq;    // sum(l0^2) minus the top bar
        float t1  = rs1;
        float t2  = rs2;
        out[0] = t01 + t0 + t1 + t2;
        out[1] = t01;
        out[2] = t0;
        out[3] = t1;
        out[4] = t2;

        g_count = 0;  // reset for next graph replay
    }
}

extern "C" void kernel_launch(void* const* d_in, const int* in_sizes, int n_in,
                              void* d_out, int out_size)
{
    const float4* a = (const float4*)d_in[0];
    const float4* b = (const float4*)d_in[1];
    const float4* c = (const float4*)d_in[2];
    float* out = (float*)d_out;

    const int nvec = in_sizes[0] / 4;

    toploss_fused<<<NBLK, NTHR>>>(a, b, c, out, nvec);
}

// round 12
// speedup vs baseline: 1.2112x; 1.2112x over previous
#include <cuda_runtime.h>
#include <math.h>

// Two-pass deterministic reduction with Programmatic Dependent Launch:
// pass2's launch overlaps pass1's tail; pass2 orders via
// cudaGridDependencySynchronize() before reading partials.

constexpr int NBLK = 2048;
constexpr int NTHR = 256;

struct Part {
    float s0, m0, s1, s2;
};

__device__ Part g_part[NBLK];

__device__ __forceinline__ float fix_len(float l) {
    return isfinite(l) ? l : 0.0f;
}

__global__ __launch_bounds__(NTHR) void pass1(
    const float4* __restrict__ a,
    const float4* __restrict__ b,
    const float4* __restrict__ c,
    int nvec)
{
    float s0 = 0.0f, s1 = 0.0f, s2 = 0.0f;
    float m0 = -INFINITY;

    const int stride = gridDim.x * blockDim.x;
    for (int i = blockIdx.x * blockDim.x + threadIdx.x; i < nvec; i += stride) {
        float4 va = __ldcs(a + i);
        float4 vb = __ldcs(b + i);
        float4 vc = __ldcs(c + i);

        float la0 = fix_len(va.x - va.y);
        float la1 = fix_len(va.z - va.w);
        s0 = fmaf(la0, la0, s0);
        s0 = fmaf(la1, la1, s0);
        m0 = fmaxf(m0, fmaxf(la0, la1));

        float lb0 = fix_len(vb.x - vb.y);
        float lb1 = fix_len(vb.z - vb.w);
        s1 = fmaf(lb0, lb0, s1);
        s1 = fmaf(lb1, lb1, s1);

        float lc0 = fix_len(vc.x - vc.y);
        float lc1 = fix_len(vc.z - vc.w);
        s2 = fmaf(lc0, lc0, s2);
        s2 = fmaf(lc1, lc1, s2);
    }

    // Warp reduce
    #pragma unroll
    for (int o = 16; o > 0; o >>= 1) {
        s0 += __shfl_xor_sync(0xffffffffu, s0, o);
        s1 += __shfl_xor_sync(0xffffffffu, s1, o);
        s2 += __shfl_xor_sync(0xffffffffu, s2, o);
        m0 = fmaxf(m0, __shfl_xor_sync(0xffffffffu, m0, o));
    }

    __shared__ float sh_s0[NTHR / 32];
    __shared__ float sh_s1[NTHR / 32];
    __shared__ float sh_s2[NTHR / 32];
    __shared__ float sh_m0[NTHR / 32];

    const int lane = threadIdx.x & 31;
    const int wid  = threadIdx.x >> 5;
    if (lane == 0) {
        sh_s0[wid] = s0;
        sh_s1[wid] = s1;
        sh_s2[wid] = s2;
        sh_m0[wid] = m0;
    }
    __syncthreads();

    if (wid == 0) {
        constexpr int NW = NTHR / 32;
        float rs0 = (lane < NW) ? sh_s0[lane] : 0.0f;
        float rs1 = (lane < NW) ? sh_s1[lane] : 0.0f;
        float rs2 = (lane < NW) ? sh_s2[lane] : 0.0f;
        float rm0 = (lane < NW) ? sh_m0[lane] : -INFINITY;
        #pragma unroll
        for (int o = NW / 2; o > 0; o >>= 1) {
            rs0 += __shfl_xor_sync(0xffffffffu, rs0, o);
            rs1 += __shfl_xor_sync(0xffffffffu, rs1, o);
            rs2 += __shfl_xor_sync(0xffffffffu, rs2, o);
            rm0 = fmaxf(rm0, __shfl_xor_sync(0xffffffffu, rm0, o));
        }
        if (lane == 0) {
            Part p;
            p.s0 = rs0; p.m0 = rm0; p.s1 = rs1; p.s2 = rs2;
            g_part[blockIdx.x] = p;
        }
    }

    // Signal PDL trigger as early as possible (fires when all CTAs have
    // triggered or exited).
    cudaTriggerProgrammaticLaunchCompletion();
}

// Pass 2: one block of 1024 threads, PDL secondary. Fixed-order fold.
__global__ __launch_bounds__(1024) void pass2(float* __restrict__ out)
{
    // Wait until pass1 is complete and its writes are visible.
    cudaGridDependencySynchronize();

    const int t = threadIdx.x;

    Part p = g_part[t];
    Part q = g_part[t + 1024];
    float s0 = p.s0 + q.s0;
    float s1 = p.s1 + q.s1;
    float s2 = p.s2 + q.s2;
    float m0 = fmaxf(p.m0, q.m0);

    #pragma unroll
    for (int o = 16; o > 0; o >>= 1) {
        s0 += __shfl_xor_sync(0xffffffffu, s0, o);
        s1 += __shfl_xor_sync(0xffffffffu, s1, o);
        s2 += __shfl_xor_sync(0xffffffffu, s2, o);
        m0 = fmaxf(m0, __shfl_xor_sync(0xffffffffu, m0, o));
    }

    __shared__ float sh_s0[32], sh_s1[32], sh_s2[32], sh_m0[32];
    const int lane = t & 31;
    const int wid  = t >> 5;
    if (lane == 0) {
        sh_s0[wid] = s0;
        sh_s1[wid] = s1;
        sh_s2[wid] = s2;
        sh_m0[wid] = m0;
    }
    __syncthreads();

    if (wid == 0) {
        float rs0 = sh_s0[lane];
        float rs1 = sh_s1[lane];
        float rs2 = sh_s2[lane];
        float rm0 = sh_m0[lane];
        #pragma unroll
        for (int o = 16; o > 0; o >>= 1) {
            rs0 += __shfl_xor_sync(0xffffffffu, rs0, o);
            rs1 += __shfl_xor_sync(0xffffffffu, rs1, o);
            rs2 += __shfl_xor_sync(0xffffffffu, rs2, o);
            rm0 = fmaxf(rm0, __shfl_xor_sync(0xffffffffu, rm0, o));
        }
        if (lane == 0) {
            float top1sq = rm0 * rm0;
            float t01 = 1.0f - top1sq;   // sum(1 - top1^2), one element
            float t0  = rs0 - top1sq;    // sum(l0^2) minus the top bar
            float t1  = rs1;
            float t2  = rs2;
            out[0] = t01 + t0 + t1 + t2;
            out[1] = t01;
            out[2] = t0;
            out[3] = t1;
            out[4] = t2;
        }
    }
}

extern "C" void kernel_launch(void* const* d_in, const int* in_sizes, int n_in,
                              void* d_out, int out_size)
{
    const float4* a = (const float4*)d_in[0];
    const float4* b = (const float4*)d_in[1];
    const float4* c = (const float4*)d_in[2];
    float* out = (float*)d_out;

    const int nvec = in_sizes[0] / 4;

    pass1<<<NBLK, NTHR>>>(a, b, c, nvec);

    // Launch pass2 with Programmatic Stream Serialization so its launch
    // overlaps pass1 execution; ordering enforced in-kernel by
    // cudaGridDependencySynchronize().
    cudaLaunchConfig_t cfg = {};
    cfg.gridDim = dim3(1, 1, 1);
    cfg.blockDim = dim3(1024, 1, 1);
    cfg.dynamicSmemBytes = 0;
    cfg.stream = 0;

    cudaLaunchAttribute attrs[1];
    attrs[0].id = cudaLaunchAttributeProgrammaticStreamSerialization;
    attrs[0].val.programmaticStreamSerializationAllowed = 1;
    cfg.attrs = attrs;
    cfg.numAttrs = 1;

    cudaLaunchKernelEx(&cfg, pass2, out);
}